// round 3
// baseline (speedup 1.0000x reference)
#include <cuda_runtime.h>
#include <cstdint>

// out[b,h,w,c] = x[b,h,w,c] + (c < 512 ? spatial_pe[h,w,c]
//                                      : pattern_pe[pattern_indices[b,h,w] % 64][c-512])
// x [64,30,30,1024] f32, pattern_indices [64,30,30] i32,
// spatial_pe [30,30,512] f32, pattern_pe [64,512] f32.  H==W==MAX_GRID==30.
//
// grid = (150, 64); block (256 thr) covers 6 consecutive pixels of one batch
// image. Thread t owns channel chunk c4 = t for all 6 pixels:
//   6 front-batched LDG.128.cs (x, streaming) + 6 LDG.128.ci (PE, L2-resident)
// per thread -> ~24 KB of DRAM reads in flight per SM, matching the
// BW_share * lat_dram requirement. Stores use .cs (write-streaming).

static constexpr int D4    = 256;   // float4 per pixel
static constexpr int HALF4 = 128;   // spatial/pattern split (float4 units)
static constexpr int HW    = 900;   // 30*30
static constexpr int PPB   = 6;     // pixels per block (900 = 150*6)
static constexpr int NUM_PAT = 64;

__global__ void __launch_bounds__(256, 4)
pe_add_kernel(const float4* __restrict__ x4,
              const int*    __restrict__ pidx,
              const float4* __restrict__ sp4,   // [900, 128] float4
              const float4* __restrict__ pp4,   // [64, 128] float4
              float4*       __restrict__ out4)
{
    const int tid  = threadIdx.x;
    const int hw0  = blockIdx.x * PPB;          // 0..894, step 6
    const int pix0 = blockIdx.y * HW + hw0;

    const long long i0 = (long long)pix0 * D4 + tid;

    // ---- front-batched x loads (streaming: read-once) ----
    float4 xv[PPB];
#pragma unroll
    for (int j = 0; j < PPB; j++)
        xv[j] = __ldcs(&x4[i0 + (long long)j * D4]);

    // ---- PE loads (L2-resident tables) ----
    float4 pe[PPB];
    if (tid < HALF4) {                           // warps 0-3: spatial half
        const float4* s = sp4 + (long long)hw0 * HALF4 + tid;
#pragma unroll
        for (int j = 0; j < PPB; j++)
            pe[j] = __ldg(&s[j * HALF4]);
    } else {                                     // warps 4-7: pattern half
        const int c = tid - HALF4;
        unsigned p[PPB];
#pragma unroll
        for (int j = 0; j < PPB; j++)            // indices first (warp-uniform)
            p[j] = (unsigned)__ldg(&pidx[pix0 + j]) % NUM_PAT;
#pragma unroll
        for (int j = 0; j < PPB; j++)
            pe[j] = __ldg(&pp4[(long long)p[j] * HALF4 + c]);
    }

    // ---- add + streaming stores ----
#pragma unroll
    for (int j = 0; j < PPB; j++) {
        xv[j].x += pe[j].x; xv[j].y += pe[j].y;
        xv[j].z += pe[j].z; xv[j].w += pe[j].w;
        __stcs(&out4[i0 + (long long)j * D4], xv[j]);
    }
}

extern "C" void kernel_launch(void* const* d_in, const int* in_sizes, int n_in,
                              void* d_out, int out_size)
{
    const float4* x4   = (const float4*)d_in[0];
    const int*    pidx = (const int*)d_in[1];
    const float4* sp4  = (const float4*)d_in[2];
    const float4* pp4  = (const float4*)d_in[3];
    float4*       out4 = (float4*)d_out;

    dim3 grid(HW / PPB, 64);   // (150, 64)
    pe_add_kernel<<<grid, 256>>>(x4, pidx, sp4, pp4, out4);
}